// round 1
// baseline (speedup 1.0000x reference)
#include <cuda_runtime.h>

#define ETA_MIN 0.6931471805599453f
#define ETA_MAX 10.0f

// Elementwise: out[i] = loss[i] > eta ? 0 : 1 - loss[i]/eta
// eta = clamp(eta_value[0], ETA_MIN, ETA_MAX)
// N = 2^25, divisible by 8 (two float4 per thread).

__global__ __launch_bounds__(256) void weights_kernel(
    const float4* __restrict__ loss4,
    const float* __restrict__ eta_value,
    float4* __restrict__ out4,
    int n4)  // number of float4 elements
{
    // One L2-broadcast scalar load per thread; cheap.
    float eta = eta_value[0];
    eta = fminf(fmaxf(eta, ETA_MIN), ETA_MAX);
    float inv_eta = 1.0f / eta;

    int i = (blockIdx.x * blockDim.x + threadIdx.x) * 2;

    // Two independent float4 loads issued back-to-back -> MLP=2 per thread,
    // 8 outstanding sectors per warp pair; grid covers all SMs many waves.
    if (i + 1 < n4) {
        float4 a = loss4[i];
        float4 b = loss4[i + 1];

        float4 ra, rb;
        ra.x = (a.x > eta) ? 0.0f : fmaf(-a.x, inv_eta, 1.0f);
        ra.y = (a.y > eta) ? 0.0f : fmaf(-a.y, inv_eta, 1.0f);
        ra.z = (a.z > eta) ? 0.0f : fmaf(-a.z, inv_eta, 1.0f);
        ra.w = (a.w > eta) ? 0.0f : fmaf(-a.w, inv_eta, 1.0f);
        rb.x = (b.x > eta) ? 0.0f : fmaf(-b.x, inv_eta, 1.0f);
        rb.y = (b.y > eta) ? 0.0f : fmaf(-b.y, inv_eta, 1.0f);
        rb.z = (b.z > eta) ? 0.0f : fmaf(-b.z, inv_eta, 1.0f);
        rb.w = (b.w > eta) ? 0.0f : fmaf(-b.w, inv_eta, 1.0f);

        out4[i] = ra;
        out4[i + 1] = rb;
    } else if (i < n4) {
        float4 a = loss4[i];
        float4 ra;
        ra.x = (a.x > eta) ? 0.0f : fmaf(-a.x, inv_eta, 1.0f);
        ra.y = (a.y > eta) ? 0.0f : fmaf(-a.y, inv_eta, 1.0f);
        ra.z = (a.z > eta) ? 0.0f : fmaf(-a.z, inv_eta, 1.0f);
        ra.w = (a.w > eta) ? 0.0f : fmaf(-a.w, inv_eta, 1.0f);
        out4[i] = ra;
    }
}

// Scalar tail kernel for any remainder elements not covered by float4 path.
__global__ void weights_tail_kernel(
    const float* __restrict__ loss,
    const float* __restrict__ eta_value,
    float* __restrict__ out,
    int start, int n)
{
    int i = start + blockIdx.x * blockDim.x + threadIdx.x;
    if (i < n) {
        float eta = eta_value[0];
        eta = fminf(fmaxf(eta, ETA_MIN), ETA_MAX);
        float v = loss[i];
        out[i] = (v > eta) ? 0.0f : 1.0f - v / eta;
    }
}

extern "C" void kernel_launch(void* const* d_in, const int* in_sizes, int n_in,
                              void* d_out, int out_size)
{
    const float* loss = (const float*)d_in[0];
    const float* eta_value = (const float*)d_in[1];
    float* out = (float*)d_out;
    int n = in_sizes[0];

    int n4 = n / 4;                 // float4 count
    int vec_elems = n4 * 4;         // elements covered by vector path
    int threads = 256;
    int per_block = threads * 2;    // two float4 per thread
    int blocks = (n4 + per_block - 1) / per_block;

    if (blocks > 0) {
        weights_kernel<<<blocks, threads>>>(
            (const float4*)loss, eta_value, (float4*)out, n4);
    }
    int tail = n - vec_elems;
    if (tail > 0) {
        int tb = (tail + 255) / 256;
        weights_tail_kernel<<<tb, 256>>>(loss, eta_value, out, vec_elems, n);
    }
}